// round 9
// baseline (speedup 1.0000x reference)
#include <cuda_runtime.h>
#include <cuda_fp16.h>

#define NNODES_MAX 100000
#define NEDGES_MAX 1600000
#define NG_MAX     1000

// ---------------- scratch (static device globals; no allocation) ----------------
__device__ int   g_deg[NNODES_MAX];
__device__ float g_dinv[NNODES_MAX];
__device__ int   g_off[NNODES_MAX + 1];
__device__ int   g_cur[NNODES_MAX];
__device__ int   g_csr[NEDGES_MAX];
__device__ unsigned long long g_sstate[128];   // decoupled-lookback scan state
// g_buf1: y1 as half [N][128] (gemm1 out, unscaled), later h2 as half [N][64]
// g_buf2: h1 as half [N][128]
// g_buf3: y2 as half [N][64]
__device__ __align__(16) float g_buf1[NNODES_MAX * 128];
__device__ __align__(16) float g_buf2[NNODES_MAX * 64];
__device__ __align__(16) float g_buf3[NNODES_MAX * 32];
// pre-split transposed weights: [n][k] half hi/lo
__device__ __align__(16) __half g_W1th[128 * 256], g_W1tl[128 * 256];
__device__ __align__(16) __half g_W2th[64 * 128],  g_W2tl[64 * 128];

// ---------------- weight convert (hi/lo split + transpose) ----------------
__global__ void k_wconv(const float* __restrict__ W1, const float* __restrict__ W2) {
    int i = blockIdx.x * blockDim.x + threadIdx.x;
    if (i < 256 * 128) {
        int k = i >> 7, n = i & 127;
        float v = W1[i];
        __half h = __float2half_rn(v);
        g_W1th[n * 256 + k] = h;
        g_W1tl[n * 256 + k] = __float2half_rn(v - __half2float(h));
    } else if (i < 256 * 128 + 128 * 64) {
        int j = i - 256 * 128;
        int k = j >> 6, n = j & 63;
        float v = W2[j];
        __half h = __float2half_rn(v);
        g_W2th[n * 128 + k] = h;
        g_W2tl[n * 128 + k] = __float2half_rn(v - __half2float(h));
    }
}

// ---------------- degree count (also resets scan state for this run) ----------------
__global__ void k_count(const int* __restrict__ dst, int E) {
    int gtid = blockIdx.x * blockDim.x + threadIdx.x;
    if (gtid < 128) g_sstate[gtid] = 0ULL;
    int stride = gridDim.x * blockDim.x;
    for (int i = gtid; i < E; i += stride)
        atomicAdd(&g_deg[dst[i]], 1);
}

// ---------------- single-pass scan: dinv + offsets + cursors (decoupled lookback) ----
// grid = ceil(n/1024) <= 98 blocks (all co-resident on 148 SMs) x 1024 threads.
__global__ void k_scanlb(int n) {
    __shared__ int wsum[32];
    __shared__ int s_prefix;
    const int bid = blockIdx.x;
    const int i = bid * 1024 + threadIdx.x;
    const int lane = threadIdx.x & 31, wid = threadIdx.x >> 5;
    if (threadIdx.x == 0) s_prefix = 0;
    int d = (i < n) ? g_deg[i] : 0;
    if (i < n) g_dinv[i] = rsqrtf((float)(d + 1));
    int x = d;
    #pragma unroll
    for (int o = 1; o < 32; o <<= 1) {
        int y = __shfl_up_sync(0xffffffffu, x, o);
        if (lane >= o) x += y;
    }
    if (lane == 31) wsum[wid] = x;
    __syncthreads();
    if (wid == 0) {
        int w = wsum[lane];
        #pragma unroll
        for (int o = 1; o < 32; o <<= 1) {
            int y = __shfl_up_sync(0xffffffffu, w, o);
            if (lane >= o) w += y;
        }
        wsum[lane] = w;
    }
    __syncthreads();
    const int incl = x + (wid > 0 ? wsum[wid - 1] : 0);
    const int btotal = wsum[31];

    // publish partial (or inclusive for block 0), then warp-0 lookback
    if (threadIdx.x == 0) {
        unsigned long long v = ((bid == 0 ? 2ULL : 1ULL) << 62) | (unsigned long long)btotal;
        atomicExch(&g_sstate[bid], v);
    }
    if (wid == 0 && bid > 0) {
        long long acc = 0;
        int j = bid - 1;
        bool done = false;
        while (!done) {
            int idx = j - lane;
            unsigned long long s;
            do {
                s = (idx >= 0) ? atomicAdd(&g_sstate[idx], 0ULL) : (2ULL << 62);
            } while (__any_sync(0xffffffffu, (s >> 62) == 0));
            unsigned im = __ballot_sync(0xffffffffu, (s >> 62) == 2ULL);
            long long val = (long long)(s & 0x3FFFFFFFFFFFFFFFULL);
            long long contrib;
            if (im) {
                int L = __ffs(im) - 1;
                contrib = (lane <= L) ? val : 0;
                done = true;
            } else {
                contrib = (idx >= 0) ? val : 0;
                j -= 32;
            }
            #pragma unroll
            for (int o = 16; o > 0; o >>= 1)
                contrib += __shfl_down_sync(0xffffffffu, contrib, o);
            if (lane == 0) acc += contrib;
        }
        if (lane == 0) {
            s_prefix = (int)acc;
            atomicExch(&g_sstate[bid],
                       (2ULL << 62) | (unsigned long long)(acc + (long long)btotal));
        }
    }
    __syncthreads();
    const int v = incl + s_prefix;
    if (i == 0) { g_off[0] = 0; g_cur[0] = 0; }
    if (i < n) {
        g_off[i + 1] = v;
        if (i + 1 < n) g_cur[i + 1] = v;
    }
}

__global__ void k_fill(const int* __restrict__ src, const int* __restrict__ dst, int E) {
    int stride = gridDim.x * blockDim.x;
    for (int e = blockIdx.x * blockDim.x + threadIdx.x; e < E; e += stride) {
        int pos = atomicAdd(&g_cur[dst[e]], 1);
        g_csr[pos] = src[e];
    }
}

// ---------------- mma / ldmatrix helpers ----------------
__device__ __forceinline__ void mma16h(float c[4], unsigned a0, unsigned a1, unsigned a2,
                                       unsigned a3, unsigned b0, unsigned b1) {
    asm("mma.sync.aligned.m16n8k16.row.col.f32.f16.f16.f32 "
        "{%0,%1,%2,%3}, {%4,%5,%6,%7}, {%8,%9}, {%0,%1,%2,%3};"
        : "+f"(c[0]), "+f"(c[1]), "+f"(c[2]), "+f"(c[3])
        : "r"(a0), "r"(a1), "r"(a2), "r"(a3), "r"(b0), "r"(b1));
}

__device__ __forceinline__ void ldsm4(unsigned& r0, unsigned& r1, unsigned& r2,
                                      unsigned& r3, unsigned addr) {
    asm volatile("ldmatrix.sync.aligned.m8n8.x4.shared.b16 {%0,%1,%2,%3}, [%4];"
                 : "=r"(r0), "=r"(r1), "=r"(r2), "=r"(r3) : "r"(addr));
}

__device__ __forceinline__ void ldsm2(unsigned& r0, unsigned& r1, unsigned addr) {
    asm volatile("ldmatrix.sync.aligned.m8n8.x2.shared.b16 {%0,%1}, [%2];"
                 : "=r"(r0), "=r"(r1) : "r"(addr));
}

// ---------------- GEMM1: 2-term fp16 (A rounded, W1 hi/lo), K=256, N=128 ----------------
__global__ __launch_bounds__(256)
void gemm1_f16(const float* __restrict__ A, __half* __restrict__ C, int M) {
    constexpr int K = 256, BN = 128, BK = 32;
    constexpr int LDA = 40, LDB = 40;
    __shared__ __half As_h[128 * LDA];
    __shared__ __half Bs_h[BN * LDB], Bs_l[BN * LDB];

    const int tid  = threadIdx.x;
    const int warp = tid >> 5, lane = tid & 31;
    const int gq   = lane >> 2, tig = lane & 3;
    const int wm   = (warp & 1) * 64;
    const int wn   = (warp >> 1) * 32;
    const int m0   = blockIdx.x * 128;

    const unsigned sA  = (unsigned)__cvta_generic_to_shared(As_h);
    const unsigned sBh = (unsigned)__cvta_generic_to_shared(Bs_h);
    const unsigned sBl = (unsigned)__cvta_generic_to_shared(Bs_l);
    const int aLaneOff = ((lane & 15) * LDA + (lane >> 4) * 8) * 2;
    const int bl15 = lane & 15;
    const int bLaneOff = ((bl15 & 7) * LDB + (bl15 >> 3) * 8) * 2;
    unsigned aBase[4], bBaseH[4], bBaseL[4];
    #pragma unroll
    for (int mt = 0; mt < 4; mt++)
        aBase[mt] = sA + (wm + mt * 16) * LDA * 2 + aLaneOff;
    #pragma unroll
    for (int nt = 0; nt < 4; nt++) {
        bBaseH[nt] = sBh + (wn + nt * 8) * LDB * 2 + bLaneOff;
        bBaseL[nt] = sBl + (wn + nt * 8) * LDB * 2 + bLaneOff;
    }

    float acc[4][4][4];
    #pragma unroll
    for (int mt = 0; mt < 4; mt++)
        #pragma unroll
        for (int nt = 0; nt < 4; nt++)
            #pragma unroll
            for (int q = 0; q < 4; q++) acc[mt][nt][q] = 0.f;

    for (int k0 = 0; k0 < K; k0 += BK) {
        #pragma unroll
        for (int it = 0; it < 4; it++) {
            int idx = it * 256 + tid;
            int r = idx >> 3, c = (idx & 7) * 4;
            int gm = m0 + r;
            float4 v = make_float4(0.f, 0.f, 0.f, 0.f);
            if (gm < M) v = *(const float4*)&A[(size_t)gm * K + k0 + c];
            uint2 p;
            *(__half2*)&p.x = __floats2half2_rn(v.x, v.y);
            *(__half2*)&p.y = __floats2half2_rn(v.z, v.w);
            *(uint2*)&As_h[r * LDA + c] = p;
        }
        #pragma unroll
        for (int it = 0; it < 2; it++) {
            int idx = it * 256 + tid;
            int n = idx >> 2, c = (idx & 3) * 8;
            *(uint4*)&Bs_h[n * LDB + c] = *(const uint4*)&g_W1th[n * 256 + k0 + c];
            *(uint4*)&Bs_l[n * LDB + c] = *(const uint4*)&g_W1tl[n * 256 + k0 + c];
        }
        __syncthreads();
        #pragma unroll
        for (int ks = 0; ks < 2; ks++) {
            const int kbB = ks * 16 * 2;
            unsigned bh[4][2], bl[4][2];
            #pragma unroll
            for (int nt = 0; nt < 4; nt++) {
                ldsm2(bh[nt][0], bh[nt][1], bBaseH[nt] + kbB);
                ldsm2(bl[nt][0], bl[nt][1], bBaseL[nt] + kbB);
            }
            #pragma unroll
            for (int mt = 0; mt < 4; mt++) {
                unsigned a0, a1, a2, a3;
                ldsm4(a0, a1, a2, a3, aBase[mt] + kbB);
                #pragma unroll
                for (int nt = 0; nt < 4; nt++) {
                    mma16h(acc[mt][nt], a0, a1, a2, a3, bh[nt][0], bh[nt][1]);
                    mma16h(acc[mt][nt], a0, a1, a2, a3, bl[nt][0], bl[nt][1]);
                }
            }
        }
        __syncthreads();
    }

    #pragma unroll
    for (int mt = 0; mt < 4; mt++) {
        int r0 = m0 + wm + mt * 16 + gq;
        int r1 = r0 + 8;
        #pragma unroll
        for (int nt = 0; nt < 4; nt++) {
            int col = wn + nt * 8 + 2 * tig;
            if (r0 < M)
                *(__half2*)&C[(size_t)r0 * BN + col] = __floats2half2_rn(acc[mt][nt][0], acc[mt][nt][1]);
            if (r1 < M)
                *(__half2*)&C[(size_t)r1 * BN + col] = __floats2half2_rn(acc[mt][nt][2], acc[mt][nt][3]);
        }
    }
}

// ---------------- GEMM2: 2-term fp16, K=128, N=64, dinv epi; row-offset aware ----------
__global__ __launch_bounds__(256)
void gemm2_f16(const __half* __restrict__ A, __half* __restrict__ C, int M, int rowOff) {
    constexpr int K = 128, BN = 64, BK = 64;
    constexpr int LDA = 72, LDB = 72;
    __shared__ __half As[128 * LDA];
    __shared__ __half Bth[BN * LDB], Btl[BN * LDB];

    const int tid  = threadIdx.x;
    const int warp = tid >> 5, lane = tid & 31;
    const int gq   = lane >> 2, tig = lane & 3;
    const int wm   = (warp & 1) * 64;
    const int wn   = (warp >> 1) * 16;
    const int m0   = blockIdx.x * 128;

    float acc[4][2][4];
    #pragma unroll
    for (int mt = 0; mt < 4; mt++)
        #pragma unroll
        for (int nt = 0; nt < 2; nt++)
            #pragma unroll
            for (int q = 0; q < 4; q++) acc[mt][nt][q] = 0.f;

    for (int k0 = 0; k0 < K; k0 += BK) {
        #pragma unroll
        for (int it = 0; it < 4; it++) {
            int idx = it * 256 + tid;
            int r = idx >> 3, c = (idx & 7) * 8;
            int gm = m0 + r;
            uint4 v = make_uint4(0u, 0u, 0u, 0u);
            if (gm < M) v = *(const uint4*)&A[(size_t)gm * K + k0 + c];
            *(uint4*)&As[r * LDA + c] = v;
        }
        #pragma unroll
        for (int it = 0; it < 2; it++) {
            int idx = it * 256 + tid;
            int n = idx >> 3, c = (idx & 7) * 8;
            *(uint4*)&Bth[n * LDB + c] = *(const uint4*)&g_W2th[n * 128 + k0 + c];
            *(uint4*)&Btl[n * LDB + c] = *(const uint4*)&g_W2tl[n * 128 + k0 + c];
        }
        __syncthreads();
        #pragma unroll
        for (int ks = 0; ks < 4; ks++) {
            const int kb = ks * 16;
            unsigned bh[2][2], bl[2][2];
            #pragma unroll
            for (int nt = 0; nt < 2; nt++) {
                int col = wn + nt * 8 + gq;
                bh[nt][0] = *(const unsigned*)&Bth[col * LDB + kb + 2 * tig];
                bh[nt][1] = *(const unsigned*)&Bth[col * LDB + kb + 2 * tig + 8];
                bl[nt][0] = *(const unsigned*)&Btl[col * LDB + kb + 2 * tig];
                bl[nt][1] = *(const unsigned*)&Btl[col * LDB + kb + 2 * tig + 8];
            }
            #pragma unroll
            for (int mt = 0; mt < 4; mt++) {
                int row = wm + mt * 16 + gq;
                unsigned a0 = *(const unsigned*)&As[row * LDA + kb + 2 * tig];
                unsigned a1 = *(const unsigned*)&As[(row + 8) * LDA + kb + 2 * tig];
                unsigned a2 = *(const unsigned*)&As[row * LDA + kb + 2 * tig + 8];
                unsigned a3 = *(const unsigned*)&As[(row + 8) * LDA + kb + 2 * tig + 8];
                #pragma unroll
                for (int nt = 0; nt < 2; nt++) {
                    mma16h(acc[mt][nt], a0, a1, a2, a3, bh[nt][0], bh[nt][1]);
                    mma16h(acc[mt][nt], a0, a1, a2, a3, bl[nt][0], bl[nt][1]);
                }
            }
        }
        __syncthreads();
    }

    #pragma unroll
    for (int mt = 0; mt < 4; mt++) {
        int r0 = m0 + wm + mt * 16 + gq;
        int r1 = r0 + 8;
        #pragma unroll
        for (int nt = 0; nt < 2; nt++) {
            int col = wn + nt * 8 + 2 * tig;
            if (r0 < M) {
                float s = g_dinv[rowOff + r0];
                *(__half2*)&C[(size_t)r0 * BN + col] =
                    __floats2half2_rn(acc[mt][nt][0] * s, acc[mt][nt][1] * s);
            }
            if (r1 < M) {
                float s = g_dinv[rowOff + r1];
                *(__half2*)&C[(size_t)r1 * BN + col] =
                    __floats2half2_rn(acc[mt][nt][2] * s, acc[mt][nt][3] * s);
            }
        }
    }
}

// ---------------- aggregation (warp per node; dinv[src] applied here) ----------------
__global__ __launch_bounds__(256)
void k_agg1(const float* __restrict__ b1, int d0, int d1) {
    int d = d0 + blockIdx.x * 8 + (threadIdx.x >> 5);
    if (d >= d1) return;
    int l = threadIdx.x & 31;
    const uint2* y = (const uint2*)g_buf1;
    float dd = g_dinv[d];
    uint2 u = y[(size_t)d * 32 + l];
    float2 f0 = __half22float2(*(__half2*)&u.x);
    float2 f1 = __half22float2(*(__half2*)&u.y);
    float a0 = f0.x * dd, a1 = f0.y * dd, a2 = f1.x * dd, a3 = f1.y * dd;
    int e = g_off[d], e1 = g_off[d + 1];
    for (; e + 4 <= e1; e += 4) {
        int s0 = g_csr[e], s1 = g_csr[e + 1], s2 = g_csr[e + 2], s3 = g_csr[e + 3];
        float d0f = g_dinv[s0], d1f = g_dinv[s1], d2f = g_dinv[s2], d3f = g_dinv[s3];
        uint2 u0 = y[(size_t)s0 * 32 + l];
        uint2 u1 = y[(size_t)s1 * 32 + l];
        uint2 u2 = y[(size_t)s2 * 32 + l];
        uint2 u3 = y[(size_t)s3 * 32 + l];
        float2 p;
        p = __half22float2(*(__half2*)&u0.x); a0 = fmaf(p.x, d0f, a0); a1 = fmaf(p.y, d0f, a1);
        p = __half22float2(*(__half2*)&u0.y); a2 = fmaf(p.x, d0f, a2); a3 = fmaf(p.y, d0f, a3);
        p = __half22float2(*(__half2*)&u1.x); a0 = fmaf(p.x, d1f, a0); a1 = fmaf(p.y, d1f, a1);
        p = __half22float2(*(__half2*)&u1.y); a2 = fmaf(p.x, d1f, a2); a3 = fmaf(p.y, d1f, a3);
        p = __half22float2(*(__half2*)&u2.x); a0 = fmaf(p.x, d2f, a0); a1 = fmaf(p.y, d2f, a1);
        p = __half22float2(*(__half2*)&u2.y); a2 = fmaf(p.x, d2f, a2); a3 = fmaf(p.y, d2f, a3);
        p = __half22float2(*(__half2*)&u3.x); a0 = fmaf(p.x, d3f, a0); a1 = fmaf(p.y, d3f, a1);
        p = __half22float2(*(__half2*)&u3.y); a2 = fmaf(p.x, d3f, a2); a3 = fmaf(p.y, d3f, a3);
    }
    for (; e < e1; e++) {
        int s0 = g_csr[e];
        float d0f = g_dinv[s0];
        uint2 u0 = y[(size_t)s0 * 32 + l];
        float2 p;
        p = __half22float2(*(__half2*)&u0.x); a0 = fmaf(p.x, d0f, a0); a1 = fmaf(p.y, d0f, a1);
        p = __half22float2(*(__half2*)&u0.y); a2 = fmaf(p.x, d0f, a2); a3 = fmaf(p.y, d0f, a3);
    }
    const float4 b = ((const float4*)b1)[l];
    uint2 o;
    *(__half2*)&o.x = __floats2half2_rn(fmaxf(a0 * dd + b.x, 0.f), fmaxf(a1 * dd + b.y, 0.f));
    *(__half2*)&o.y = __floats2half2_rn(fmaxf(a2 * dd + b.z, 0.f), fmaxf(a3 * dd + b.w, 0.f));
    ((uint2*)g_buf2)[(size_t)d * 32 + l] = o;
}

// h2 (half, into g_buf1) = dinv[d]*(y2[d] + sum y2[s]) + b2
__global__ __launch_bounds__(256)
void k_agg2(const float* __restrict__ b2, int N) {
    int d = blockIdx.x * 8 + (threadIdx.x >> 5);
    if (d >= N) return;
    int l = threadIdx.x & 31;
    const __half2* y = (const __half2*)g_buf3;
    float2 acc = __half22float2(y[(size_t)d * 32 + l]);
    int e = g_off[d], e1 = g_off[d + 1];
    for (; e + 4 <= e1; e += 4) {
        int s0 = g_csr[e], s1 = g_csr[e + 1], s2 = g_csr[e + 2], s3 = g_csr[e + 3];
        float2 v0 = __half22float2(y[(size_t)s0 * 32 + l]);
        float2 v1 = __half22float2(y[(size_t)s1 * 32 + l]);
        float2 v2 = __half22float2(y[(size_t)s2 * 32 + l]);
        float2 v3 = __half22float2(y[(size_t)s3 * 32 + l]);
        acc.x += v0.x + v1.x + v2.x + v3.x;
        acc.y += v0.y + v1.y + v2.y + v3.y;
    }
    for (; e < e1; e++) {
        float2 v = __half22float2(y[(size_t)g_csr[e] * 32 + l]);
        acc.x += v.x; acc.y += v.y;
    }
    float s = g_dinv[d];
    const float2 b = ((const float2*)b2)[l];
    ((__half2*)g_buf1)[(size_t)d * 32 + l] =
        __floats2half2_rn(acc.x * s + b.x, acc.y * s + b.y);
}

// ---------------- fused head (h2 half) ----------------
__global__ __launch_bounds__(256)
void k_head(const int* __restrict__ batch, const float* __restrict__ fcW,
            const float* __restrict__ fcb, float* __restrict__ out, int N) {
    __shared__ int s_lo, s_hi;
    __shared__ float s_red[256];
    __shared__ float s_mean[64];
    __shared__ float s_logit[4];
    const int gph = blockIdx.x;
    const int tid = threadIdx.x;
    if (tid == 0) {
        int lo = 0, hi = N;
        while (lo < hi) { int m = (lo + hi) >> 1; if (batch[m] < gph) lo = m + 1; else hi = m; }
        s_lo = lo;
        int lo2 = lo, hi2 = N;
        while (lo2 < hi2) { int m = (lo2 + hi2) >> 1; if (batch[m] < gph + 1) lo2 = m + 1; else hi2 = m; }
        s_hi = lo2;
    }
    __syncthreads();
    const int lo = s_lo, hi = s_hi;
    const float inv = 1.f / fmaxf((float)(hi - lo), 1.f);
    const int f = tid & 63, sub = tid >> 6;
    const __half* h2 = (const __half*)g_buf1;
    float sum = 0.f;
    for (int i = lo + sub; i < hi; i += 4) sum += __half2float(h2[(size_t)i * 64 + f]);
    s_red[tid] = sum;
    __syncthreads();
    if (tid < 64) {
        float t = s_red[tid] + s_red[tid + 64] + s_red[tid + 128] + s_red[tid + 192];
        s_mean[tid] = t * inv;
    }
    __syncthreads();
    if (tid < 4) {
        float l = fcb[tid];
        #pragma unroll 8
        for (int k = 0; k < 64; k++) l += s_mean[k] * fcW[k * 4 + tid];
        s_logit[tid] = l;
    }
    __syncthreads();
    if (tid == 0) {
        float l0 = s_logit[0], l1 = s_logit[1], l2 = s_logit[2], l3 = s_logit[3];
        float m = fmaxf(fmaxf(l0, l1), fmaxf(l2, l3));
        float s = expf(l0 - m) + expf(l1 - m) + expf(l2 - m) + expf(l3 - m);
        float ls = m + logf(s);
        out[gph * 4 + 0] = l0 - ls;
        out[gph * 4 + 1] = l1 - ls;
        out[gph * 4 + 2] = l2 - ls;
        out[gph * 4 + 3] = l3 - ls;
    }
}

// ---------------- launch: fork GEMM1 || CSR build; pipeline agg1/gemm2 ----------------
extern "C" void kernel_launch(void* const* d_in, const int* in_sizes, int n_in,
                              void* d_out, int out_size) {
    const float* x     = (const float*)d_in[0];
    const int*   ei    = (const int*)d_in[1];
    const int*   batch = (const int*)d_in[2];
    const float* W1    = (const float*)d_in[3];
    const float* b1    = (const float*)d_in[4];
    const float* W2    = (const float*)d_in[5];
    const float* b2    = (const float*)d_in[6];
    const float* fcW   = (const float*)d_in[7];
    const float* fcb   = (const float*)d_in[8];
    float* out = (float*)d_out;

    const int N = in_sizes[0] / 256;
    const int E = in_sizes[1] / 2;
    const int G = out_size / 4;
    const int* src = ei;
    const int* dst = ei + E;

    static cudaStream_t s2 = [] {
        cudaStream_t s; cudaStreamCreateWithFlags(&s, cudaStreamNonBlocking); return s;
    }();
    static cudaEvent_t ev1, ev2, evA0, evA1, evG;
    static bool evInit = [] {
        cudaEventCreateWithFlags(&ev1,  cudaEventDisableTiming);
        cudaEventCreateWithFlags(&ev2,  cudaEventDisableTiming);
        cudaEventCreateWithFlags(&evA0, cudaEventDisableTiming);
        cudaEventCreateWithFlags(&evA1, cudaEventDisableTiming);
        cudaEventCreateWithFlags(&evG,  cudaEventDisableTiming);
        return true;
    }();
    (void)evInit;

    float *b1p, *b2p, *b3p;
    int *degp;
    cudaGetSymbolAddress((void**)&b1p, g_buf1);
    cudaGetSymbolAddress((void**)&b2p, g_buf2);
    cudaGetSymbolAddress((void**)&b3p, g_buf3);
    cudaGetSymbolAddress((void**)&degp, g_deg);
    __half* y1h = (__half*)b1p;
    __half* h1h = (__half*)b2p;
    __half* y2h = (__half*)b3p;

    const int nscan = (N + 1023) / 1024;
    const int gm    = (N + 127) / 128;

    // chunk split for agg1/gemm2 pipeline (multiple of 128)
    int c0 = ((N / 2 + 127) / 128) * 128;
    if (c0 > N) c0 = N;
    const int c1 = N - c0;

    // fork: tensor branch (weights convert + GEMM1) on s2
    cudaEventRecord(ev1, 0);
    cudaStreamWaitEvent(s2, ev1, 0);
    k_wconv<<<160, 256, 0, s2>>>(W1, W2);
    gemm1_f16<<<gm, 256, 0, s2>>>(x, y1h, N);
    cudaEventRecord(ev2, s2);

    // prep branch (CSR build) on main stream
    cudaMemsetAsync(degp, 0, (size_t)N * sizeof(int), 0);
    k_count<<<1184, 256>>>(dst, E);
    k_scanlb<<<nscan, 1024>>>(N);
    k_fill<<<1184, 256>>>(src, dst, E);

    // join, then pipelined tail: agg1(c) -> gemm2(c) overlapped across chunks
    cudaStreamWaitEvent(0, ev2, 0);
    k_agg1<<<(c0 + 7) / 8, 256>>>(b1, 0, c0);
    cudaEventRecord(evA0, 0);
    if (c1 > 0) {
        k_agg1<<<(c1 + 7) / 8, 256>>>(b1, c0, N);
        cudaEventRecord(evA1, 0);
    }
    cudaStreamWaitEvent(s2, evA0, 0);
    gemm2_f16<<<(c0 + 127) / 128, 256, 0, s2>>>(h1h, y2h, c0, 0);
    if (c1 > 0) {
        cudaStreamWaitEvent(s2, evA1, 0);
        gemm2_f16<<<(c1 + 127) / 128, 256, 0, s2>>>(h1h + (size_t)c0 * 128,
                                                    y2h + (size_t)c0 * 64, c1, c0);
    }
    cudaEventRecord(evG, s2);
    cudaStreamWaitEvent(0, evG, 0);
    k_agg2<<<(N + 7) / 8, 256>>>(b2, N);
    k_head<<<G, 256>>>(batch, fcW, fcb, out, N);
}

// round 11
// speedup vs baseline: 1.1179x; 1.1179x over previous
#include <cuda_runtime.h>
#include <cuda_fp16.h>

#define NNODES_MAX 100000
#define NEDGES_MAX 1600000
#define NG_MAX     1000

// ---------------- scratch (static device globals; no allocation) ----------------
__device__ int   g_deg[NNODES_MAX];
__device__ float g_dinv[NNODES_MAX];
__device__ int   g_off[NNODES_MAX + 1];
__device__ int   g_cur[NNODES_MAX];
__device__ int   g_csr[NEDGES_MAX];
__device__ unsigned long long g_sstate[128];   // decoupled-lookback scan state
// g_buf1: y1 as half [N][128] (gemm1 out, unscaled), later h2 as half [N][64]
// g_buf2: h1 as half [N][128]
// g_buf3: y2 as half [N][64]
__device__ __align__(16) float g_buf1[NNODES_MAX * 128];
__device__ __align__(16) float g_buf2[NNODES_MAX * 64];
__device__ __align__(16) float g_buf3[NNODES_MAX * 32];
// transposed fp16 weights: [n][k]
__device__ __align__(16) __half g_W1t[128 * 256];
__device__ __align__(16) __half g_W2t[64 * 128];

// ---------------- weight convert (fp16 + transpose) ----------------
__global__ void k_wconv(const float* __restrict__ W1, const float* __restrict__ W2) {
    int i = blockIdx.x * blockDim.x + threadIdx.x;
    if (i < 256 * 128) {
        int k = i >> 7, n = i & 127;
        g_W1t[n * 256 + k] = __float2half_rn(W1[i]);
    } else if (i < 256 * 128 + 128 * 64) {
        int j = i - 256 * 128;
        int k = j >> 6, n = j & 63;
        g_W2t[n * 128 + k] = __float2half_rn(W2[j]);
    }
}

// ---------------- degree count (also resets scan state for this run) ----------------
__global__ void k_count(const int* __restrict__ dst, int E) {
    int gtid = blockIdx.x * blockDim.x + threadIdx.x;
    if (gtid < 128) g_sstate[gtid] = 0ULL;
    int stride = gridDim.x * blockDim.x;
    for (int i = gtid; i < E; i += stride)
        atomicAdd(&g_deg[dst[i]], 1);
}

// ---------------- single-pass scan: dinv + offsets + cursors (decoupled lookback) ----
__global__ void k_scanlb(int n) {
    __shared__ int wsum[32];
    __shared__ int s_prefix;
    const int bid = blockIdx.x;
    const int i = bid * 1024 + threadIdx.x;
    const int lane = threadIdx.x & 31, wid = threadIdx.x >> 5;
    if (threadIdx.x == 0) s_prefix = 0;
    int d = (i < n) ? g_deg[i] : 0;
    if (i < n) g_dinv[i] = rsqrtf((float)(d + 1));
    int x = d;
    #pragma unroll
    for (int o = 1; o < 32; o <<= 1) {
        int y = __shfl_up_sync(0xffffffffu, x, o);
        if (lane >= o) x += y;
    }
    if (lane == 31) wsum[wid] = x;
    __syncthreads();
    if (wid == 0) {
        int w = wsum[lane];
        #pragma unroll
        for (int o = 1; o < 32; o <<= 1) {
            int y = __shfl_up_sync(0xffffffffu, w, o);
            if (lane >= o) w += y;
        }
        wsum[lane] = w;
    }
    __syncthreads();
    const int incl = x + (wid > 0 ? wsum[wid - 1] : 0);
    const int btotal = wsum[31];

    if (threadIdx.x == 0) {
        unsigned long long v = ((bid == 0 ? 2ULL : 1ULL) << 62) | (unsigned long long)btotal;
        atomicExch(&g_sstate[bid], v);
    }
    if (wid == 0 && bid > 0) {
        long long acc = 0;
        int j = bid - 1;
        bool done = false;
        while (!done) {
            int idx = j - lane;
            unsigned long long s;
            do {
                s = (idx >= 0) ? atomicAdd(&g_sstate[idx], 0ULL) : (2ULL << 62);
            } while (__any_sync(0xffffffffu, (s >> 62) == 0));
            unsigned im = __ballot_sync(0xffffffffu, (s >> 62) == 2ULL);
            long long val = (long long)(s & 0x3FFFFFFFFFFFFFFFULL);
            long long contrib;
            if (im) {
                int L = __ffs(im) - 1;
                contrib = (lane <= L) ? val : 0;
                done = true;
            } else {
                contrib = (idx >= 0) ? val : 0;
                j -= 32;
            }
            #pragma unroll
            for (int o = 16; o > 0; o >>= 1)
                contrib += __shfl_down_sync(0xffffffffu, contrib, o);
            if (lane == 0) acc += contrib;
        }
        if (lane == 0) {
            s_prefix = (int)acc;
            atomicExch(&g_sstate[bid],
                       (2ULL << 62) | (unsigned long long)(acc + (long long)btotal));
        }
    }
    __syncthreads();
    const int v = incl + s_prefix;
    if (i == 0) { g_off[0] = 0; g_cur[0] = 0; }
    if (i < n) {
        g_off[i + 1] = v;
        if (i + 1 < n) g_cur[i + 1] = v;
    }
}

__global__ void k_fill(const int* __restrict__ src, const int* __restrict__ dst, int E) {
    int stride = gridDim.x * blockDim.x;
    for (int e = blockIdx.x * blockDim.x + threadIdx.x; e < E; e += stride) {
        int pos = atomicAdd(&g_cur[dst[e]], 1);
        g_csr[pos] = src[e];
    }
}

// ---------------- mma / ldmatrix helpers ----------------
__device__ __forceinline__ void mma16h(float c[4], unsigned a0, unsigned a1, unsigned a2,
                                       unsigned a3, unsigned b0, unsigned b1) {
    asm("mma.sync.aligned.m16n8k16.row.col.f32.f16.f16.f32 "
        "{%0,%1,%2,%3}, {%4,%5,%6,%7}, {%8,%9}, {%0,%1,%2,%3};"
        : "+f"(c[0]), "+f"(c[1]), "+f"(c[2]), "+f"(c[3])
        : "r"(a0), "r"(a1), "r"(a2), "r"(a3), "r"(b0), "r"(b1));
}

__device__ __forceinline__ void ldsm4(unsigned& r0, unsigned& r1, unsigned& r2,
                                      unsigned& r3, unsigned addr) {
    asm volatile("ldmatrix.sync.aligned.m8n8.x4.shared.b16 {%0,%1,%2,%3}, [%4];"
                 : "=r"(r0), "=r"(r1), "=r"(r2), "=r"(r3) : "r"(addr));
}

__device__ __forceinline__ void ldsm2(unsigned& r0, unsigned& r1, unsigned addr) {
    asm volatile("ldmatrix.sync.aligned.m8n8.x2.shared.b16 {%0,%1}, [%2];"
                 : "=r"(r0), "=r"(r1) : "r"(addr));
}

// ---------------- GEMM1: fp16 (A rounded, W1 fp16), K=256, N=128, reg-prefetch -------
// y1[m][n] = sum_k x[m][k]*W1[k][n]   (half out, NO dinv — applied in agg1)
__global__ __launch_bounds__(256)
void gemm1_f16(const float* __restrict__ A, __half* __restrict__ C, int M) {
    constexpr int K = 256, BN = 128, BK = 32;
    constexpr int LDA = 40, LDB = 40;   // halves; rows 80B apart -> ldmatrix conflict-free
    __shared__ __half As[128 * LDA];
    __shared__ __half Bs[BN * LDB];

    const int tid  = threadIdx.x;
    const int warp = tid >> 5, lane = tid & 31;
    const int gq   = lane >> 2, tig = lane & 3;
    const int wm   = (warp & 1) * 64;
    const int wn   = (warp >> 1) * 32;
    const int m0   = blockIdx.x * 128;

    const unsigned sA = (unsigned)__cvta_generic_to_shared(As);
    const unsigned sB = (unsigned)__cvta_generic_to_shared(Bs);
    const int aLaneOff = ((lane & 15) * LDA + (lane >> 4) * 8) * 2;
    const int bl15 = lane & 15;
    const int bLaneOff = ((bl15 & 7) * LDB + (bl15 >> 3) * 8) * 2;
    unsigned aBase[4], bBase[4];
    #pragma unroll
    for (int mt = 0; mt < 4; mt++)
        aBase[mt] = sA + (wm + mt * 16) * LDA * 2 + aLaneOff;
    #pragma unroll
    for (int nt = 0; nt < 4; nt++)
        bBase[nt] = sB + (wn + nt * 8) * LDB * 2 + bLaneOff;

    // A-tile staging indices (per thread: 4 float4 = one 128x32 tile across 256 thr)
    int aR[4], aC[4];
    #pragma unroll
    for (int it = 0; it < 4; it++) {
        int idx = it * 256 + tid;
        aR[it] = idx >> 3;
        aC[it] = (idx & 7) * 4;
    }
    // B-tile staging indices (2 uint4 per thread = 128x32 halves)
    int bN[2], bC[2];
    #pragma unroll
    for (int it = 0; it < 2; it++) {
        int idx = it * 256 + tid;
        bN[it] = idx >> 2;
        bC[it] = (idx & 3) * 8;
    }

    float acc[4][4][4];
    #pragma unroll
    for (int mt = 0; mt < 4; mt++)
        #pragma unroll
        for (int nt = 0; nt < 4; nt++)
            #pragma unroll
            for (int q = 0; q < 4; q++) acc[mt][nt][q] = 0.f;

    // prologue: load tile 0 into registers
    float4 aReg[4];
    uint4  bReg[2];
    #pragma unroll
    for (int it = 0; it < 4; it++) {
        int gm = m0 + aR[it];
        aReg[it] = (gm < M) ? *(const float4*)&A[(size_t)gm * K + aC[it]]
                            : make_float4(0.f, 0.f, 0.f, 0.f);
    }
    #pragma unroll
    for (int it = 0; it < 2; it++)
        bReg[it] = *(const uint4*)&g_W1t[bN[it] * 256 + bC[it]];

    for (int k0 = 0; k0 < K; k0 += BK) {
        // stage registers -> smem
        #pragma unroll
        for (int it = 0; it < 4; it++) {
            uint2 p;
            *(__half2*)&p.x = __floats2half2_rn(aReg[it].x, aReg[it].y);
            *(__half2*)&p.y = __floats2half2_rn(aReg[it].z, aReg[it].w);
            *(uint2*)&As[aR[it] * LDA + aC[it]] = p;
        }
        #pragma unroll
        for (int it = 0; it < 2; it++)
            *(uint4*)&Bs[bN[it] * LDB + bC[it]] = bReg[it];
        __syncthreads();

        // prefetch next tile (overlaps with MMA below)
        if (k0 + BK < K) {
            #pragma unroll
            for (int it = 0; it < 4; it++) {
                int gm = m0 + aR[it];
                aReg[it] = (gm < M) ? *(const float4*)&A[(size_t)gm * K + k0 + BK + aC[it]]
                                    : make_float4(0.f, 0.f, 0.f, 0.f);
            }
            #pragma unroll
            for (int it = 0; it < 2; it++)
                bReg[it] = *(const uint4*)&g_W1t[bN[it] * 256 + k0 + BK + bC[it]];
        }

        #pragma unroll
        for (int ks = 0; ks < 2; ks++) {
            const int kbB = ks * 16 * 2;
            unsigned bf[4][2];
            #pragma unroll
            for (int nt = 0; nt < 4; nt++)
                ldsm2(bf[nt][0], bf[nt][1], bBase[nt] + kbB);
            #pragma unroll
            for (int mt = 0; mt < 4; mt++) {
                unsigned a0, a1, a2, a3;
                ldsm4(a0, a1, a2, a3, aBase[mt] + kbB);
                #pragma unroll
                for (int nt = 0; nt < 4; nt++)
                    mma16h(acc[mt][nt], a0, a1, a2, a3, bf[nt][0], bf[nt][1]);
            }
        }
        __syncthreads();
    }

    #pragma unroll
    for (int mt = 0; mt < 4; mt++) {
        int r0 = m0 + wm + mt * 16 + gq;
        int r1 = r0 + 8;
        #pragma unroll
        for (int nt = 0; nt < 4; nt++) {
            int col = wn + nt * 8 + 2 * tig;
            if (r0 < M)
                *(__half2*)&C[(size_t)r0 * BN + col] = __floats2half2_rn(acc[mt][nt][0], acc[mt][nt][1]);
            if (r1 < M)
                *(__half2*)&C[(size_t)r1 * BN + col] = __floats2half2_rn(acc[mt][nt][2], acc[mt][nt][3]);
        }
    }
}

// ---------------- GEMM2: fp16, K=128, N=64, dinv epilogue ----------------
__global__ __launch_bounds__(256)
void gemm2_f16(const __half* __restrict__ A, __half* __restrict__ C, int M) {
    constexpr int K = 128, BN = 64, BK = 64;
    constexpr int LDA = 72, LDB = 72;
    __shared__ __half As[128 * LDA];
    __shared__ __half Bt[BN * LDB];

    const int tid  = threadIdx.x;
    const int warp = tid >> 5, lane = tid & 31;
    const int gq   = lane >> 2, tig = lane & 3;
    const int wm   = (warp & 1) * 64;
    const int wn   = (warp >> 1) * 16;
    const int m0   = blockIdx.x * 128;

    float acc[4][2][4];
    #pragma unroll
    for (int mt = 0; mt < 4; mt++)
        #pragma unroll
        for (int nt = 0; nt < 2; nt++)
            #pragma unroll
            for (int q = 0; q < 4; q++) acc[mt][nt][q] = 0.f;

    for (int k0 = 0; k0 < K; k0 += BK) {
        #pragma unroll
        for (int it = 0; it < 4; it++) {
            int idx = it * 256 + tid;
            int r = idx >> 3, c = (idx & 7) * 8;
            int gm = m0 + r;
            uint4 v = make_uint4(0u, 0u, 0u, 0u);
            if (gm < M) v = *(const uint4*)&A[(size_t)gm * K + k0 + c];
            *(uint4*)&As[r * LDA + c] = v;
        }
        {
            int idx = tid;   // 64n x 64k halves = 256 uint4
            int n = idx >> 2, c = (idx & 3) * 16;
            *(uint4*)&Bt[n * LDB + c]     = *(const uint4*)&g_W2t[n * 128 + k0 + c];
            *(uint4*)&Bt[n * LDB + c + 8] = *(const uint4*)&g_W2t[n * 128 + k0 + c + 8];
        }
        __syncthreads();
        #pragma unroll
        for (int ks = 0; ks < 4; ks++) {
            const int kb = ks * 16;
            unsigned bf[2][2];
            #pragma unroll
            for (int nt = 0; nt < 2; nt++) {
                int col = wn + nt * 8 + gq;
                bf[nt][0] = *(const unsigned*)&Bt[col * LDB + kb + 2 * tig];
                bf[nt][1] = *(const unsigned*)&Bt[col * LDB + kb + 2 * tig + 8];
            }
            #pragma unroll
            for (int mt = 0; mt < 4; mt++) {
                int row = wm + mt * 16 + gq;
                unsigned a0 = *(const unsigned*)&As[row * LDA + kb + 2 * tig];
                unsigned a1 = *(const unsigned*)&As[(row + 8) * LDA + kb + 2 * tig];
                unsigned a2 = *(const unsigned*)&As[row * LDA + kb + 2 * tig + 8];
                unsigned a3 = *(const unsigned*)&As[(row + 8) * LDA + kb + 2 * tig + 8];
                #pragma unroll
                for (int nt = 0; nt < 2; nt++)
                    mma16h(acc[mt][nt], a0, a1, a2, a3, bf[nt][0], bf[nt][1]);
            }
        }
        __syncthreads();
    }

    #pragma unroll
    for (int mt = 0; mt < 4; mt++) {
        int r0 = m0 + wm + mt * 16 + gq;
        int r1 = r0 + 8;
        #pragma unroll
        for (int nt = 0; nt < 2; nt++) {
            int col = wn + nt * 8 + 2 * tig;
            if (r0 < M) {
                float s = g_dinv[r0];
                *(__half2*)&C[(size_t)r0 * BN + col] =
                    __floats2half2_rn(acc[mt][nt][0] * s, acc[mt][nt][1] * s);
            }
            if (r1 < M) {
                float s = g_dinv[r1];
                *(__half2*)&C[(size_t)r1 * BN + col] =
                    __floats2half2_rn(acc[mt][nt][2] * s, acc[mt][nt][3] * s);
            }
        }
    }
}

// ---------------- aggregation (warp per node; dinv[src] applied here) ----------------
__global__ __launch_bounds__(256)
void k_agg1(const float* __restrict__ b1, int N) {
    int d = blockIdx.x * 8 + (threadIdx.x >> 5);
    if (d >= N) return;
    int l = threadIdx.x & 31;
    const uint2* y = (const uint2*)g_buf1;
    float dd = g_dinv[d];
    uint2 u = y[(size_t)d * 32 + l];
    float2 f0 = __half22float2(*(__half2*)&u.x);
    float2 f1 = __half22float2(*(__half2*)&u.y);
    float a0 = f0.x * dd, a1 = f0.y * dd, a2 = f1.x * dd, a3 = f1.y * dd;
    int e = g_off[d], e1 = g_off[d + 1];
    for (; e + 4 <= e1; e += 4) {
        int s0 = g_csr[e], s1 = g_csr[e + 1], s2 = g_csr[e + 2], s3 = g_csr[e + 3];
        float d0f = g_dinv[s0], d1f = g_dinv[s1], d2f = g_dinv[s2], d3f = g_dinv[s3];
        uint2 u0 = y[(size_t)s0 * 32 + l];
        uint2 u1 = y[(size_t)s1 * 32 + l];
        uint2 u2 = y[(size_t)s2 * 32 + l];
        uint2 u3 = y[(size_t)s3 * 32 + l];
        float2 p;
        p = __half22float2(*(__half2*)&u0.x); a0 = fmaf(p.x, d0f, a0); a1 = fmaf(p.y, d0f, a1);
        p = __half22float2(*(__half2*)&u0.y); a2 = fmaf(p.x, d0f, a2); a3 = fmaf(p.y, d0f, a3);
        p = __half22float2(*(__half2*)&u1.x); a0 = fmaf(p.x, d1f, a0); a1 = fmaf(p.y, d1f, a1);
        p = __half22float2(*(__half2*)&u1.y); a2 = fmaf(p.x, d1f, a2); a3 = fmaf(p.y, d1f, a3);
        p = __half22float2(*(__half2*)&u2.x); a0 = fmaf(p.x, d2f, a0); a1 = fmaf(p.y, d2f, a1);
        p = __half22float2(*(__half2*)&u2.y); a2 = fmaf(p.x, d2f, a2); a3 = fmaf(p.y, d2f, a3);
        p = __half22float2(*(__half2*)&u3.x); a0 = fmaf(p.x, d3f, a0); a1 = fmaf(p.y, d3f, a1);
        p = __half22float2(*(__half2*)&u3.y); a2 = fmaf(p.x, d3f, a2); a3 = fmaf(p.y, d3f, a3);
    }
    for (; e < e1; e++) {
        int s0 = g_csr[e];
        float d0f = g_dinv[s0];
        uint2 u0 = y[(size_t)s0 * 32 + l];
        float2 p;
        p = __half22float2(*(__half2*)&u0.x); a0 = fmaf(p.x, d0f, a0); a1 = fmaf(p.y, d0f, a1);
        p = __half22float2(*(__half2*)&u0.y); a2 = fmaf(p.x, d0f, a2); a3 = fmaf(p.y, d0f, a3);
    }
    const float4 b = ((const float4*)b1)[l];
    uint2 o;
    *(__half2*)&o.x = __floats2half2_rn(fmaxf(a0 * dd + b.x, 0.f), fmaxf(a1 * dd + b.y, 0.f));
    *(__half2*)&o.y = __floats2half2_rn(fmaxf(a2 * dd + b.z, 0.f), fmaxf(a3 * dd + b.w, 0.f));
    ((uint2*)g_buf2)[(size_t)d * 32 + l] = o;
}

// h2 (half, into g_buf1) = dinv[d]*(y2[d] + sum y2[s]) + b2
__global__ __launch_bounds__(256)
void k_agg2(const float* __restrict__ b2, int N) {
    int d = blockIdx.x * 8 + (threadIdx.x >> 5);
    if (d >= N) return;
    int l = threadIdx.x & 31;
    const __half2* y = (const __half2*)g_buf3;
    float2 acc = __half22float2(y[(size_t)d * 32 + l]);
    int e = g_off[d], e1 = g_off[d + 1];
    for (; e + 4 <= e1; e += 4) {
        int s0 = g_csr[e], s1 = g_csr[e + 1], s2 = g_csr[e + 2], s3 = g_csr[e + 3];
        float2 v0 = __half22float2(y[(size_t)s0 * 32 + l]);
        float2 v1 = __half22float2(y[(size_t)s1 * 32 + l]);
        float2 v2 = __half22float2(y[(size_t)s2 * 32 + l]);
        float2 v3 = __half22float2(y[(size_t)s3 * 32 + l]);
        acc.x += v0.x + v1.x + v2.x + v3.x;
        acc.y += v0.y + v1.y + v2.y + v3.y;
    }
    for (; e < e1; e++) {
        float2 v = __half22float2(y[(size_t)g_csr[e] * 32 + l]);
        acc.x += v.x; acc.y += v.y;
    }
    float s = g_dinv[d];
    const float2 b = ((const float2*)b2)[l];
    ((__half2*)g_buf1)[(size_t)d * 32 + l] =
        __floats2half2_rn(acc.x * s + b.x, acc.y * s + b.y);
}

// ---------------- fused head (h2 half) ----------------
__global__ __launch_bounds__(256)
void k_head(const int* __restrict__ batch, const float* __restrict__ fcW,
            const float* __restrict__ fcb, float* __restrict__ out, int N) {
    __shared__ int s_lo, s_hi;
    __shared__ float s_red[256];
    __shared__ float s_mean[64];
    __shared__ float s_logit[4];
    const int gph = blockIdx.x;
    const int tid = threadIdx.x;
    if (tid == 0) {
        int lo = 0, hi = N;
        while (lo < hi) { int m = (lo + hi) >> 1; if (batch[m] < gph) lo = m + 1; else hi = m; }
        s_lo = lo;
        int lo2 = lo, hi2 = N;
        while (lo2 < hi2) { int m = (lo2 + hi2) >> 1; if (batch[m] < gph + 1) lo2 = m + 1; else hi2 = m; }
        s_hi = lo2;
    }
    __syncthreads();
    const int lo = s_lo, hi = s_hi;
    const float inv = 1.f / fmaxf((float)(hi - lo), 1.f);
    const int f = tid & 63, sub = tid >> 6;
    const __half* h2 = (const __half*)g_buf1;
    float sum = 0.f;
    for (int i = lo + sub; i < hi; i += 4) sum += __half2float(h2[(size_t)i * 64 + f]);
    s_red[tid] = sum;
    __syncthreads();
    if (tid < 64) {
        float t = s_red[tid] + s_red[tid + 64] + s_red[tid + 128] + s_red[tid + 192];
        s_mean[tid] = t * inv;
    }
    __syncthreads();
    if (tid < 4) {
        float l = fcb[tid];
        #pragma unroll 8
        for (int k = 0; k < 64; k++) l += s_mean[k] * fcW[k * 4 + tid];
        s_logit[tid] = l;
    }
    __syncthreads();
    if (tid == 0) {
        float l0 = s_logit[0], l1 = s_logit[1], l2 = s_logit[2], l3 = s_logit[3];
        float m = fmaxf(fmaxf(l0, l1), fmaxf(l2, l3));
        float s = expf(l0 - m) + expf(l1 - m) + expf(l2 - m) + expf(l3 - m);
        float ls = m + logf(s);
        out[gph * 4 + 0] = l0 - ls;
        out[gph * 4 + 1] = l1 - ls;
        out[gph * 4 + 2] = l2 - ls;
        out[gph * 4 + 3] = l3 - ls;
    }
}

// ---------------- launch (forked capture stream: GEMM1 || CSR build) ----------------
extern "C" void kernel_launch(void* const* d_in, const int* in_sizes, int n_in,
                              void* d_out, int out_size) {
    const float* x     = (const float*)d_in[0];
    const int*   ei    = (const int*)d_in[1];
    const int*   batch = (const int*)d_in[2];
    const float* W1    = (const float*)d_in[3];
    const float* b1    = (const float*)d_in[4];
    const float* W2    = (const float*)d_in[5];
    const float* b2    = (const float*)d_in[6];
    const float* fcW   = (const float*)d_in[7];
    const float* fcb   = (const float*)d_in[8];
    float* out = (float*)d_out;

    const int N = in_sizes[0] / 256;
    const int E = in_sizes[1] / 2;
    const int G = out_size / 4;
    const int* src = ei;
    const int* dst = ei + E;

    static cudaStream_t s2 = [] {
        cudaStream_t s; cudaStreamCreateWithFlags(&s, cudaStreamNonBlocking); return s;
    }();
    static cudaEvent_t ev1 = [] {
        cudaEvent_t e; cudaEventCreateWithFlags(&e, cudaEventDisableTiming); return e;
    }();
    static cudaEvent_t ev2 = [] {
        cudaEvent_t e; cudaEventCreateWithFlags(&e, cudaEventDisableTiming); return e;
    }();

    float *b1p, *b2p, *b3p;
    int *degp;
    cudaGetSymbolAddress((void**)&b1p, g_buf1);
    cudaGetSymbolAddress((void**)&b2p, g_buf2);
    cudaGetSymbolAddress((void**)&b3p, g_buf3);
    cudaGetSymbolAddress((void**)&degp, g_deg);
    __half* y1h = (__half*)b1p;
    __half* h1h = (__half*)b2p;
    __half* y2h = (__half*)b3p;

    const int nscan = (N + 1023) / 1024;
    const int gm    = (N + 127) / 128;
    const int ga    = (N + 7) / 8;

    // fork: tensor branch (weights convert + GEMM1) on s2
    cudaEventRecord(ev1, 0);
    cudaStreamWaitEvent(s2, ev1, 0);
    k_wconv<<<160, 256, 0, s2>>>(W1, W2);
    gemm1_f16<<<gm, 256, 0, s2>>>(x, y1h, N);
    cudaEventRecord(ev2, s2);

    // prep branch (CSR build) on main stream
    cudaMemsetAsync(degp, 0, (size_t)N * sizeof(int), 0);
    k_count<<<1184, 256>>>(dst, E);
    k_scanlb<<<nscan, 1024>>>(N);
    k_fill<<<1184, 256>>>(src, dst, E);

    // join, then serial tail
    cudaStreamWaitEvent(0, ev2, 0);
    k_agg1<<<ga, 256>>>(b1, N);
    gemm2_f16<<<gm, 256>>>(h1h, y2h, N);
    k_agg2<<<ga, 256>>>(b2, N);
    k_head<<<G, 256>>>(batch, fcW, fcb, out, N);
}

// round 13
// speedup vs baseline: 1.1198x; 1.0017x over previous
#include <cuda_runtime.h>
#include <cuda_fp16.h>

#define NNODES_MAX 100000
#define NEDGES_MAX 1600000
#define NG_MAX     1000

// ---------------- scratch (static device globals; no allocation) ----------------
__device__ int   g_deg[NNODES_MAX];
__device__ float g_dinv[NNODES_MAX];
__device__ int   g_off[NNODES_MAX + 1];
__device__ int   g_cur[NNODES_MAX];
__device__ int   g_csr[NEDGES_MAX];
__device__ unsigned long long g_sstate[128];   // decoupled-lookback scan state
// g_buf1: y1 as e4m3 [N][128] (gemm1 out, unscaled), later h2 as half [N][64]
// g_buf2: h1 as half [N][128]  (gemm2 MMA input stays fp16)
// g_buf3: y2 as e4m3 [N][64]
__device__ __align__(16) float g_buf1[NNODES_MAX * 64];
__device__ __align__(16) float g_buf2[NNODES_MAX * 64];
__device__ __align__(16) float g_buf3[NNODES_MAX * 16];
// transposed fp16 weights: [n][k]
__device__ __align__(16) __half g_W1t[128 * 256];
__device__ __align__(16) __half g_W2t[64 * 128];

// ---------------- fp8 helpers ----------------
__device__ __forceinline__ unsigned short f2e4m3x2(float lo, float hi) {
    unsigned short r;
    asm("cvt.rn.satfinite.e4m3x2.f32 %0, %1, %2;" : "=h"(r) : "f"(hi), "f"(lo));
    return r;   // byte0 = e4m3(lo), byte1 = e4m3(hi)
}
__device__ __forceinline__ __half2 e4m3x2_h2(unsigned short v) {
    unsigned r;
    asm("cvt.rn.f16x2.e4m3x2 %0, %1;" : "=r"(r) : "h"(v));
    return *(__half2*)&r;
}

// ---------------- weight convert (fp16 + transpose) ----------------
__global__ void k_wconv(const float* __restrict__ W1, const float* __restrict__ W2) {
    int i = blockIdx.x * blockDim.x + threadIdx.x;
    if (i < 256 * 128) {
        int k = i >> 7, n = i & 127;
        g_W1t[n * 256 + k] = __float2half_rn(W1[i]);
    } else if (i < 256 * 128 + 128 * 64) {
        int j = i - 256 * 128;
        int k = j >> 6, n = j & 63;
        g_W2t[n * 128 + k] = __float2half_rn(W2[j]);
    }
}

// ---------------- degree count (also resets scan state for this run) ----------------
__global__ void k_count(const int* __restrict__ dst, int E) {
    int gtid = blockIdx.x * blockDim.x + threadIdx.x;
    if (gtid < 128) g_sstate[gtid] = 0ULL;
    int stride = gridDim.x * blockDim.x;
    for (int i = gtid; i < E; i += stride)
        atomicAdd(&g_deg[dst[i]], 1);
}

// ---------------- single-pass scan: dinv + offsets + cursors (decoupled lookback) ----
__global__ void k_scanlb(int n) {
    __shared__ int wsum[32];
    __shared__ int s_prefix;
    const int bid = blockIdx.x;
    const int i = bid * 1024 + threadIdx.x;
    const int lane = threadIdx.x & 31, wid = threadIdx.x >> 5;
    if (threadIdx.x == 0) s_prefix = 0;
    int d = (i < n) ? g_deg[i] : 0;
    if (i < n) g_dinv[i] = rsqrtf((float)(d + 1));
    int x = d;
    #pragma unroll
    for (int o = 1; o < 32; o <<= 1) {
        int y = __shfl_up_sync(0xffffffffu, x, o);
        if (lane >= o) x += y;
    }
    if (lane == 31) wsum[wid] = x;
    __syncthreads();
    if (wid == 0) {
        int w = wsum[lane];
        #pragma unroll
        for (int o = 1; o < 32; o <<= 1) {
            int y = __shfl_up_sync(0xffffffffu, w, o);
            if (lane >= o) w += y;
        }
        wsum[lane] = w;
    }
    __syncthreads();
    const int incl = x + (wid > 0 ? wsum[wid - 1] : 0);
    const int btotal = wsum[31];

    if (threadIdx.x == 0) {
        unsigned long long v = ((bid == 0 ? 2ULL : 1ULL) << 62) | (unsigned long long)btotal;
        atomicExch(&g_sstate[bid], v);
    }
    if (wid == 0 && bid > 0) {
        long long acc = 0;
        int j = bid - 1;
        bool done = false;
        while (!done) {
            int idx = j - lane;
            unsigned long long s;
            do {
                s = (idx >= 0) ? atomicAdd(&g_sstate[idx], 0ULL) : (2ULL << 62);
            } while (__any_sync(0xffffffffu, (s >> 62) == 0));
            unsigned im = __ballot_sync(0xffffffffu, (s >> 62) == 2ULL);
            long long val = (long long)(s & 0x3FFFFFFFFFFFFFFFULL);
            long long contrib;
            if (im) {
                int L = __ffs(im) - 1;
                contrib = (lane <= L) ? val : 0;
                done = true;
            } else {
                contrib = (idx >= 0) ? val : 0;
                j -= 32;
            }
            #pragma unroll
            for (int o = 16; o > 0; o >>= 1)
                contrib += __shfl_down_sync(0xffffffffu, contrib, o);
            if (lane == 0) acc += contrib;
        }
        if (lane == 0) {
            s_prefix = (int)acc;
            atomicExch(&g_sstate[bid],
                       (2ULL << 62) | (unsigned long long)(acc + (long long)btotal));
        }
    }
    __syncthreads();
    const int v = incl + s_prefix;
    if (i == 0) { g_off[0] = 0; g_cur[0] = 0; }
    if (i < n) {
        g_off[i + 1] = v;
        if (i + 1 < n) g_cur[i + 1] = v;
    }
}

__global__ void k_fill(const int* __restrict__ src, const int* __restrict__ dst, int E) {
    int stride = gridDim.x * blockDim.x;
    for (int e = blockIdx.x * blockDim.x + threadIdx.x; e < E; e += stride) {
        int pos = atomicAdd(&g_cur[dst[e]], 1);
        g_csr[pos] = src[e];
    }
}

// ---------------- mma / ldmatrix helpers ----------------
__device__ __forceinline__ void mma16h(float c[4], unsigned a0, unsigned a1, unsigned a2,
                                       unsigned a3, unsigned b0, unsigned b1) {
    asm("mma.sync.aligned.m16n8k16.row.col.f32.f16.f16.f32 "
        "{%0,%1,%2,%3}, {%4,%5,%6,%7}, {%8,%9}, {%0,%1,%2,%3};"
        : "+f"(c[0]), "+f"(c[1]), "+f"(c[2]), "+f"(c[3])
        : "r"(a0), "r"(a1), "r"(a2), "r"(a3), "r"(b0), "r"(b1));
}

__device__ __forceinline__ void ldsm4(unsigned& r0, unsigned& r1, unsigned& r2,
                                      unsigned& r3, unsigned addr) {
    asm volatile("ldmatrix.sync.aligned.m8n8.x4.shared.b16 {%0,%1,%2,%3}, [%4];"
                 : "=r"(r0), "=r"(r1), "=r"(r2), "=r"(r3) : "r"(addr));
}

__device__ __forceinline__ void ldsm2(unsigned& r0, unsigned& r1, unsigned addr) {
    asm volatile("ldmatrix.sync.aligned.m8n8.x2.shared.b16 {%0,%1}, [%2];"
                 : "=r"(r0), "=r"(r1) : "r"(addr));
}

// ---------------- GEMM1: fp16 MMA, K=256, N=128, reg-prefetch; e4m3 out ----------------
// y1[m][n] = sum_k x[m][k]*W1[k][n]   (fp8 out, NO dinv — applied in agg1)
__global__ __launch_bounds__(256)
void gemm1_f16(const float* __restrict__ A, unsigned char* __restrict__ C, int M) {
    constexpr int K = 256, BN = 128, BK = 32;
    constexpr int LDA = 40, LDB = 40;
    __shared__ __half As[128 * LDA];
    __shared__ __half Bs[BN * LDB];

    const int tid  = threadIdx.x;
    const int warp = tid >> 5, lane = tid & 31;
    const int gq   = lane >> 2, tig = lane & 3;
    const int wm   = (warp & 1) * 64;
    const int wn   = (warp >> 1) * 32;
    const int m0   = blockIdx.x * 128;

    const unsigned sA = (unsigned)__cvta_generic_to_shared(As);
    const unsigned sB = (unsigned)__cvta_generic_to_shared(Bs);
    const int aLaneOff = ((lane & 15) * LDA + (lane >> 4) * 8) * 2;
    const int bl15 = lane & 15;
    const int bLaneOff = ((bl15 & 7) * LDB + (bl15 >> 3) * 8) * 2;
    unsigned aBase[4], bBase[4];
    #pragma unroll
    for (int mt = 0; mt < 4; mt++)
        aBase[mt] = sA + (wm + mt * 16) * LDA * 2 + aLaneOff;
    #pragma unroll
    for (int nt = 0; nt < 4; nt++)
        bBase[nt] = sB + (wn + nt * 8) * LDB * 2 + bLaneOff;

    int aR[4], aC[4];
    #pragma unroll
    for (int it = 0; it < 4; it++) {
        int idx = it * 256 + tid;
        aR[it] = idx >> 3;
        aC[it] = (idx & 7) * 4;
    }
    int bN[2], bC[2];
    #pragma unroll
    for (int it = 0; it < 2; it++) {
        int idx = it * 256 + tid;
        bN[it] = idx >> 2;
        bC[it] = (idx & 3) * 8;
    }

    float acc[4][4][4];
    #pragma unroll
    for (int mt = 0; mt < 4; mt++)
        #pragma unroll
        for (int nt = 0; nt < 4; nt++)
            #pragma unroll
            for (int q = 0; q < 4; q++) acc[mt][nt][q] = 0.f;

    float4 aReg[4];
    uint4  bReg[2];
    #pragma unroll
    for (int it = 0; it < 4; it++) {
        int gm = m0 + aR[it];
        aReg[it] = (gm < M) ? *(const float4*)&A[(size_t)gm * K + aC[it]]
                            : make_float4(0.f, 0.f, 0.f, 0.f);
    }
    #pragma unroll
    for (int it = 0; it < 2; it++)
        bReg[it] = *(const uint4*)&g_W1t[bN[it] * 256 + bC[it]];

    for (int k0 = 0; k0 < K; k0 += BK) {
        #pragma unroll
        for (int it = 0; it < 4; it++) {
            uint2 p;
            *(__half2*)&p.x = __floats2half2_rn(aReg[it].x, aReg[it].y);
            *(__half2*)&p.y = __floats2half2_rn(aReg[it].z, aReg[it].w);
            *(uint2*)&As[aR[it] * LDA + aC[it]] = p;
        }
        #pragma unroll
        for (int it = 0; it < 2; it++)
            *(uint4*)&Bs[bN[it] * LDB + bC[it]] = bReg[it];
        __syncthreads();

        if (k0 + BK < K) {
            #pragma unroll
            for (int it = 0; it < 4; it++) {
                int gm = m0 + aR[it];
                aReg[it] = (gm < M) ? *(const float4*)&A[(size_t)gm * K + k0 + BK + aC[it]]
                                    : make_float4(0.f, 0.f, 0.f, 0.f);
            }
            #pragma unroll
            for (int it = 0; it < 2; it++)
                bReg[it] = *(const uint4*)&g_W1t[bN[it] * 256 + k0 + BK + bC[it]];
        }

        #pragma unroll
        for (int ks = 0; ks < 2; ks++) {
            const int kbB = ks * 16 * 2;
            unsigned bf[4][2];
            #pragma unroll
            for (int nt = 0; nt < 4; nt++)
                ldsm2(bf[nt][0], bf[nt][1], bBase[nt] + kbB);
            #pragma unroll
            for (int mt = 0; mt < 4; mt++) {
                unsigned a0, a1, a2, a3;
                ldsm4(a0, a1, a2, a3, aBase[mt] + kbB);
                #pragma unroll
                for (int nt = 0; nt < 4; nt++)
                    mma16h(acc[mt][nt], a0, a1, a2, a3, bf[nt][0], bf[nt][1]);
            }
        }
        __syncthreads();
    }

    #pragma unroll
    for (int mt = 0; mt < 4; mt++) {
        int r0 = m0 + wm + mt * 16 + gq;
        int r1 = r0 + 8;
        #pragma unroll
        for (int nt = 0; nt < 4; nt++) {
            int col = wn + nt * 8 + 2 * tig;
            if (r0 < M)
                *(unsigned short*)&C[(size_t)r0 * BN + col] = f2e4m3x2(acc[mt][nt][0], acc[mt][nt][1]);
            if (r1 < M)
                *(unsigned short*)&C[(size_t)r1 * BN + col] = f2e4m3x2(acc[mt][nt][2], acc[mt][nt][3]);
        }
    }
}

// ---------------- GEMM2: fp16 MMA, K=128, N=64, dinv epilogue; e4m3 out ----------------
__global__ __launch_bounds__(256)
void gemm2_f16(const __half* __restrict__ A, unsigned char* __restrict__ C, int M) {
    constexpr int K = 128, BN = 64, BK = 64;
    constexpr int LDA = 72, LDB = 72;
    __shared__ __half As[128 * LDA];
    __shared__ __half Bt[BN * LDB];

    const int tid  = threadIdx.x;
    const int warp = tid >> 5, lane = tid & 31;
    const int gq   = lane >> 2, tig = lane & 3;
    const int wm   = (warp & 1) * 64;
    const int wn   = (warp >> 1) * 16;
    const int m0   = blockIdx.x * 128;

    float acc[4][2][4];
    #pragma unroll
    for (int mt = 0; mt < 4; mt++)
        #pragma unroll
        for (int nt = 0; nt < 2; nt++)
            #pragma unroll
            for (int q = 0; q < 4; q++) acc[mt][nt][q] = 0.f;

    for (int k0 = 0; k0 < K; k0 += BK) {
        #pragma unroll
        for (int it = 0; it < 4; it++) {
            int idx = it * 256 + tid;
            int r = idx >> 3, c = (idx & 7) * 8;
            int gm = m0 + r;
            uint4 v = make_uint4(0u, 0u, 0u, 0u);
            if (gm < M) v = *(const uint4*)&A[(size_t)gm * K + k0 + c];
            *(uint4*)&As[r * LDA + c] = v;
        }
        {
            int idx = tid;
            int n = idx >> 2, c = (idx & 3) * 16;
            *(uint4*)&Bt[n * LDB + c]     = *(const uint4*)&g_W2t[n * 128 + k0 + c];
            *(uint4*)&Bt[n * LDB + c + 8] = *(const uint4*)&g_W2t[n * 128 + k0 + c + 8];
        }
        __syncthreads();
        #pragma unroll
        for (int ks = 0; ks < 4; ks++) {
            const int kb = ks * 16;
            unsigned bf[2][2];
            #pragma unroll
            for (int nt = 0; nt < 2; nt++) {
                int col = wn + nt * 8 + gq;
                bf[nt][0] = *(const unsigned*)&Bt[col * LDB + kb + 2 * tig];
                bf[nt][1] = *(const unsigned*)&Bt[col * LDB + kb + 2 * tig + 8];
            }
            #pragma unroll
            for (int mt = 0; mt < 4; mt++) {
                int row = wm + mt * 16 + gq;
                unsigned a0 = *(const unsigned*)&As[row * LDA + kb + 2 * tig];
                unsigned a1 = *(const unsigned*)&As[(row + 8) * LDA + kb + 2 * tig];
                unsigned a2 = *(const unsigned*)&As[row * LDA + kb + 2 * tig + 8];
                unsigned a3 = *(const unsigned*)&As[(row + 8) * LDA + kb + 2 * tig + 8];
                #pragma unroll
                for (int nt = 0; nt < 2; nt++)
                    mma16h(acc[mt][nt], a0, a1, a2, a3, bf[nt][0], bf[nt][1]);
            }
        }
        __syncthreads();
    }

    #pragma unroll
    for (int mt = 0; mt < 4; mt++) {
        int r0 = m0 + wm + mt * 16 + gq;
        int r1 = r0 + 8;
        #pragma unroll
        for (int nt = 0; nt < 2; nt++) {
            int col = wn + nt * 8 + 2 * tig;
            if (r0 < M) {
                float s = g_dinv[r0];
                *(unsigned short*)&C[(size_t)r0 * BN + col] =
                    f2e4m3x2(acc[mt][nt][0] * s, acc[mt][nt][1] * s);
            }
            if (r1 < M) {
                float s = g_dinv[r1];
                *(unsigned short*)&C[(size_t)r1 * BN + col] =
                    f2e4m3x2(acc[mt][nt][2] * s, acc[mt][nt][3] * s);
            }
        }
    }
}

// ---------------- agg1: warp/node; y1 fp8 gathers, fp32 accum; h1 half out -----------
__global__ __launch_bounds__(256)
void k_agg1(const float* __restrict__ b1, int N) {
    int d = blockIdx.x * 8 + (threadIdx.x >> 5);
    if (d >= N) return;
    int l = threadIdx.x & 31;
    const unsigned* y = (const unsigned*)g_buf1;   // fp8[.][128] -> 32 uints/row
    float dd = g_dinv[d];
    unsigned u = y[(size_t)d * 32 + l];
    float2 f0 = __half22float2(e4m3x2_h2((unsigned short)(u & 0xffffu)));
    float2 f1 = __half22float2(e4m3x2_h2((unsigned short)(u >> 16)));
    float a0 = f0.x * dd, a1 = f0.y * dd, a2 = f1.x * dd, a3 = f1.y * dd;
    int e = g_off[d], e1 = g_off[d + 1];
    for (; e + 4 <= e1; e += 4) {
        int s0 = g_csr[e], s1 = g_csr[e + 1], s2 = g_csr[e + 2], s3 = g_csr[e + 3];
        float d0f = g_dinv[s0], d1f = g_dinv[s1], d2f = g_dinv[s2], d3f = g_dinv[s3];
        unsigned u0 = y[(size_t)s0 * 32 + l];
        unsigned u1 = y[(size_t)s1 * 32 + l];
        unsigned u2 = y[(size_t)s2 * 32 + l];
        unsigned u3 = y[(size_t)s3 * 32 + l];
        float2 p;
        p = __half22float2(e4m3x2_h2((unsigned short)(u0 & 0xffffu))); a0 = fmaf(p.x, d0f, a0); a1 = fmaf(p.y, d0f, a1);
        p = __half22float2(e4m3x2_h2((unsigned short)(u0 >> 16)));     a2 = fmaf(p.x, d0f, a2); a3 = fmaf(p.y, d0f, a3);
        p = __half22float2(e4m3x2_h2((unsigned short)(u1 & 0xffffu))); a0 = fmaf(p.x, d1f, a0); a1 = fmaf(p.y, d1f, a1);
        p = __half22float2(e4m3x2_h2((unsigned short)(u1 >> 16)));     a2 = fmaf(p.x, d1f, a2); a3 = fmaf(p.y, d1f, a3);
        p = __half22float2(e4m3x2_h2((unsigned short)(u2 & 0xffffu))); a0 = fmaf(p.x, d2f, a0); a1 = fmaf(p.y, d2f, a1);
        p = __half22float2(e4m3x2_h2((unsigned short)(u2 >> 16)));     a2 = fmaf(p.x, d2f, a2); a3 = fmaf(p.y, d2f, a3);
        p = __half22float2(e4m3x2_h2((unsigned short)(u3 & 0xffffu))); a0 = fmaf(p.x, d3f, a0); a1 = fmaf(p.y, d3f, a1);
        p = __half22float2(e4m3x2_h2((unsigned short)(u3 >> 16)));     a2 = fmaf(p.x, d3f, a2); a3 = fmaf(p.y, d3f, a3);
    }
    for (; e < e1; e++) {
        int s0 = g_csr[e];
        float d0f = g_dinv[s0];
        unsigned u0 = y[(size_t)s0 * 32 + l];
        float2 p;
        p = __half22float2(e4m3x2_h2((unsigned short)(u0 & 0xffffu))); a0 = fmaf(p.x, d0f, a0); a1 = fmaf(p.y, d0f, a1);
        p = __half22float2(e4m3x2_h2((unsigned short)(u0 >> 16)));     a2 = fmaf(p.x, d0f, a2); a3 = fmaf(p.y, d0f, a3);
    }
    const float4 b = ((const float4*)b1)[l];
    uint2 o;
    *(__half2*)&o.x = __floats2half2_rn(fmaxf(a0 * dd + b.x, 0.f), fmaxf(a1 * dd + b.y, 0.f));
    *(__half2*)&o.y = __floats2half2_rn(fmaxf(a2 * dd + b.z, 0.f), fmaxf(a3 * dd + b.w, 0.f));
    ((uint2*)g_buf2)[(size_t)d * 32 + l] = o;
}

// ---------------- agg2: warp/node; y2 fp8 gathers; h2 half out (into g_buf1) ---------
__global__ __launch_bounds__(256)
void k_agg2(const float* __restrict__ b2, int N) {
    int d = blockIdx.x * 8 + (threadIdx.x >> 5);
    if (d >= N) return;
    int l = threadIdx.x & 31;
    const unsigned short* y = (const unsigned short*)g_buf3;   // fp8[.][64] -> 32 ushort/row
    float2 acc = __half22float2(e4m3x2_h2(y[(size_t)d * 32 + l]));
    int e = g_off[d], e1 = g_off[d + 1];
    for (; e + 4 <= e1; e += 4) {
        int s0 = g_csr[e], s1 = g_csr[e + 1], s2 = g_csr[e + 2], s3 = g_csr[e + 3];
        float2 v0 = __half22float2(e4m3x2_h2(y[(size_t)s0 * 32 + l]));
        float2 v1 = __half22float2(e4m3x2_h2(y[(size_t)s1 * 32 + l]));
        float2 v2 = __half22float2(e4m3x2_h2(y[(size_t)s2 * 32 + l]));
        float2 v3 = __half22float2(e4m3x2_h2(y[(size_t)s3 * 32 + l]));
        acc.x += v0.x + v1.x + v2.x + v3.x;
        acc.y += v0.y + v1.y + v2.y + v3.y;
    }
    for (; e < e1; e++) {
        float2 v = __half22float2(e4m3x2_h2(y[(size_t)g_csr[e] * 32 + l]));
        acc.x += v.x; acc.y += v.y;
    }
    float s = g_dinv[d];
    const float2 b = ((const float2*)b2)[l];
    ((__half2*)g_buf1)[(size_t)d * 32 + l] =
        __floats2half2_rn(acc.x * s + b.x, acc.y * s + b.y);
}

// ---------------- fused head (h2 half) ----------------
__global__ __launch_bounds__(256)
void k_head(const int* __restrict__ batch, const float* __restrict__ fcW,
            const float* __restrict__ fcb, float* __restrict__ out, int N) {
    __shared__ int s_lo, s_hi;
    __shared__ float s_red[256];
    __shared__ float s_mean[64];
    __shared__ float s_logit[4];
    const int gph = blockIdx.x;
    const int tid = threadIdx.x;
    if (tid == 0) {
        int lo = 0, hi = N;
        while (lo < hi) { int m = (lo + hi) >> 1; if (batch[m] < gph) lo = m + 1; else hi = m; }
        s_lo = lo;
        int lo2 = lo, hi2 = N;
        while (lo2 < hi2) { int m = (lo2 + hi2) >> 1; if (batch[m] < gph + 1) lo2 = m + 1; else hi2 = m; }
        s_hi = lo2;
    }
    __syncthreads();
    const int lo = s_lo, hi = s_hi;
    const float inv = 1.f / fmaxf((float)(hi - lo), 1.f);
    const int f = tid & 63, sub = tid >> 6;
    const __half* h2 = (const __half*)g_buf1;
    float sum = 0.f;
    for (int i = lo + sub; i < hi; i += 4) sum += __half2float(h2[(size_t)i * 64 + f]);
    s_red[tid] = sum;
    __syncthreads();
    if (tid < 64) {
        float t = s_red[tid] + s_red[tid + 64] + s_red[tid + 128] + s_red[tid + 192];
        s_mean[tid] = t * inv;
    }
    __syncthreads();
    if (tid < 4) {
        float l = fcb[tid];
        #pragma unroll 8
        for (int k = 0; k < 64; k++) l += s_mean[k] * fcW[k * 4 + tid];
        s_logit[tid] = l;
    }
    __syncthreads();
    if (tid == 0) {
        float l0 = s_logit[0], l1 = s_logit[1], l2 = s_logit[2], l3 = s_logit[3];
        float m = fmaxf(fmaxf(l0, l1), fmaxf(l2, l3));
        float s = expf(l0 - m) + expf(l1 - m) + expf(l2 - m) + expf(l3 - m);
        float ls = m + logf(s);
        out[gph * 4 + 0] = l0 - ls;
        out[gph * 4 + 1] = l1 - ls;
        out[gph * 4 + 2] = l2 - ls;
        out[gph * 4 + 3] = l3 - ls;
    }
}

// ---------------- launch (forked capture stream: GEMM1 || CSR build) ----------------
extern "C" void kernel_launch(void* const* d_in, const int* in_sizes, int n_in,
                              void* d_out, int out_size) {
    const float* x     = (const float*)d_in[0];
    const int*   ei    = (const int*)d_in[1];
    const int*   batch = (const int*)d_in[2];
    const float* W1    = (const float*)d_in[3];
    const float* b1    = (const float*)d_in[4];
    const float* W2    = (const float*)d_in[5];
    const float* b2    = (const float*)d_in[6];
    const float* fcW   = (const float*)d_in[7];
    const float* fcb   = (const float*)d_in[8];
    float* out = (float*)d_out;

    const int N = in_sizes[0] / 256;
    const int E = in_sizes[1] / 2;
    const int G = out_size / 4;
    const int* src = ei;
    const int* dst = ei + E;

    static cudaStream_t s2 = [] {
        cudaStream_t s; cudaStreamCreateWithFlags(&s, cudaStreamNonBlocking); return s;
    }();
    static cudaEvent_t ev1 = [] {
        cudaEvent_t e; cudaEventCreateWithFlags(&e, cudaEventDisableTiming); return e;
    }();
    static cudaEvent_t ev2 = [] {
        cudaEvent_t e; cudaEventCreateWithFlags(&e, cudaEventDisableTiming); return e;
    }();

    float *b1p, *b2p, *b3p;
    int *degp;
    cudaGetSymbolAddress((void**)&b1p, g_buf1);
    cudaGetSymbolAddress((void**)&b2p, g_buf2);
    cudaGetSymbolAddress((void**)&b3p, g_buf3);
    cudaGetSymbolAddress((void**)&degp, g_deg);
    unsigned char* y1q = (unsigned char*)b1p;
    __half*        h1h = (__half*)b2p;
    unsigned char* y2q = (unsigned char*)b3p;

    const int nscan = (N + 1023) / 1024;
    const int gm    = (N + 127) / 128;
    const int ga    = (N + 7) / 8;

    // fork: tensor branch (weights convert + GEMM1) on s2
    cudaEventRecord(ev1, 0);
    cudaStreamWaitEvent(s2, ev1, 0);
    k_wconv<<<160, 256, 0, s2>>>(W1, W2);
    gemm1_f16<<<gm, 256, 0, s2>>>(x, y1q, N);
    cudaEventRecord(ev2, s2);

    // prep branch (CSR build) on main stream
    cudaMemsetAsync(degp, 0, (size_t)N * sizeof(int), 0);
    k_count<<<1184, 256>>>(dst, E);
    k_scanlb<<<nscan, 1024>>>(N);
    k_fill<<<1184, 256>>>(src, dst, E);

    // join, then serial tail
    cudaStreamWaitEvent(0, ev2, 0);
    k_agg1<<<ga, 256>>>(b1, N);
    gemm2_f16<<<gm, 256>>>(h1h, y2q, N);
    k_agg2<<<ga, 256>>>(b2, N);
    k_head<<<G, 256>>>(batch, fcW, fcb, out, N);
}